// round 4
// baseline (speedup 1.0000x reference)
#include <cuda_runtime.h>
#include <cstdint>

#define NUM_BITS 16
#define THETA 8
#define HN 4096
#define FF 128
#define CC 10
#define BB 64
#define P0 (FF * NUM_BITS)   // 2048

#define OUT_BLOCKS 96
#define LH_TOTAL (3 * HN)                      // 12288
#define LH_PER_BLOCK (LH_TOTAL / OUT_BLOCKS)   // 128

typedef unsigned long long u64;

// Scratch (device globals: no allocation allowed in kernel_launch)
__device__ u64 g_act[P0];          // layer-0 input masks
__device__ u64 g_fired[3 * HN];    // per-layer fired masks
__device__ float g_part[OUT_BLOCKS * BB * CC];    // output partial sums

// -------------------------------------------------------------------------
__global__ void zero_fired_kernel() {
    int i = blockIdx.x * blockDim.x + threadIdx.x;
    if (i < 3 * HN) g_fired[i] = 0ull;
}

// -------------------------------------------------------------------------
// Encode: x[B,F] -> g_act[p], p = f*16 + t, bit b = (x[b,f] >= (t+1)/17)
// -------------------------------------------------------------------------
__global__ void encode_kernel(const float* __restrict__ x) {
    int p = blockIdx.x * blockDim.x + threadIdx.x;
    if (p >= P0) return;
    int f = p >> 4;
    int t = p & 15;
    float thr = (float)(t + 1) * (1.0f / (float)(NUM_BITS + 1));
    u64 m = 0ull;
#pragma unroll
    for (int b = 0; b < BB; b++) {
        float v = __ldg(&x[b * FF + f]);
        m |= ((u64)(v >= thr)) << b;
    }
    g_act[p] = m;
}

// -------------------------------------------------------------------------
// Bit-sliced arithmetic over 64 batches (one bit per batch per plane).
// Counter value per batch <= 32 -> 6 planes exact.
// -------------------------------------------------------------------------
__device__ __forceinline__ void add6(u64* c, u64 m) {
    u64 carry = m;
#pragma unroll
    for (int i = 0; i < 6; i++) {
        u64 t = c[i];
        c[i] = t ^ carry;
        carry = t & carry;
    }
}

__device__ __forceinline__ void addvec6(u64* a, const u64* b) {
    u64 carry = 0ull;
#pragma unroll
    for (int i = 0; i < 6; i++) {
        u64 ai = a[i], bi = b[i];
        u64 x = ai ^ bi;
        a[i] = x ^ carry;
        carry = (ai & bi) | (carry & x);
    }
}

// -------------------------------------------------------------------------
// Layer: one warp per (neuron, segment). Each lane streams its strided slice
// of W[h,s,:] with uint4 loads, and on a nonzero weight (rare) ripple-adds
// the 64-batch activation mask into its bit-sliced POS/NEG counters.
// No cross-lane sync in the hot loop. End: shfl butterfly bit-sliced sum,
// then bit-sliced (POS - NEG >= THETA) for all 64 batches at once.
// -------------------------------------------------------------------------
__device__ __forceinline__ void proc_vec(uint4 v, int i, int lane,
                                         const u64* __restrict__ act,
                                         u64* POSp, u64* NEGp) {
    if (v.x | v.y | v.z | v.w) {
        int pbase = i * 128 + lane * 4;
        unsigned c[4] = {v.x, v.y, v.z, v.w};
#pragma unroll
        for (int j = 0; j < 4; j++) {
            if (c[j]) {
                u64 m = __ldg(&act[pbase + j]);
                // +1.0f -> positive int, -1.0f -> negative int
                u64 mp = ((int)c[j] > 0) ? m : 0ull;
                add6(POSp, mp);
                add6(NEGp, m ^ mp);
            }
        }
    }
}

template <int P>
__global__ __launch_bounds__(256) void layer_kernel(
    const float* __restrict__ W,
    const u64* __restrict__ act,
    u64* __restrict__ fired) {
    int gw = (blockIdx.x * blockDim.x + threadIdx.x) >> 5;  // (h,s) flat
    int lane = threadIdx.x & 31;
    if (gw >= 2 * HN) return;

    const uint4* row = (const uint4*)(W + (size_t)gw * (size_t)P);
    u64 POSp[6] = {0, 0, 0, 0, 0, 0};
    u64 NEGp[6] = {0, 0, 0, 0, 0, 0};

    constexpr int NIT = P / 128;   // 16 (P=2048) or 32 (P=4096)
#pragma unroll
    for (int i = 0; i < NIT; i += 4) {
        uint4 v0 = __ldg(&row[(i + 0) * 32 + lane]);
        uint4 v1 = __ldg(&row[(i + 1) * 32 + lane]);
        uint4 v2 = __ldg(&row[(i + 2) * 32 + lane]);
        uint4 v3 = __ldg(&row[(i + 3) * 32 + lane]);
        proc_vec(v0, i + 0, lane, act, POSp, NEGp);
        proc_vec(v1, i + 1, lane, act, POSp, NEGp);
        proc_vec(v2, i + 2, lane, act, POSp, NEGp);
        proc_vec(v3, i + 3, lane, act, POSp, NEGp);
    }

    // Cross-lane bit-sliced reduction (butterfly -> every lane has totals).
#pragma unroll
    for (int off = 16; off > 0; off >>= 1) {
        u64 tP[6], tN[6];
#pragma unroll
        for (int i = 0; i < 6; i++) tP[i] = __shfl_xor_sync(0xffffffffu, POSp[i], off);
#pragma unroll
        for (int i = 0; i < 6; i++) tN[i] = __shfl_xor_sync(0xffffffffu, NEGp[i], off);
        addvec6(POSp, tP);
        addvec6(NEGp, tN);
    }

    if (lane == 0) {
        // R = POS - NEG in 7-bit two's complement: R = POS + ~NEG + 1.
        u64 carry = ~0ull;   // the "+1" for every batch
        u64 R3, R4, R5;
        u64 r[6];
#pragma unroll
        for (int i = 0; i < 6; i++) {
            u64 a = POSp[i], b = ~NEGp[i];
            u64 x = a ^ b;
            r[i] = x ^ carry;
            carry = (a & b) | (carry & x);
        }
        R3 = r[3]; R4 = r[4]; R5 = r[5];
        // sign plane R6 = ~carry; fired iff R >= 8 (R in [-32,32]):
        // sign==0 && (bit3|bit4|bit5)
        u64 fm = carry & (R3 | R4 | R5);
        if (fm) atomicOr(&fired[gw >> 1], fm);
    }
}

// -------------------------------------------------------------------------
// Output stage 1: partial sums over (l,h) slices.
// -------------------------------------------------------------------------
__global__ __launch_bounds__(640) void out_partial_kernel(
    const float* __restrict__ oW,
    const u64* __restrict__ fired,
    float* __restrict__ part) {
    int t = threadIdx.x;          // 0..639
    int b = t & 63;
    int c = t >> 6;
    int start = blockIdx.x * LH_PER_BLOCK;
    float acc = 0.0f;
#pragma unroll 8
    for (int i = 0; i < LH_PER_BLOCK; i++) {
        int lh = start + i;       // flat l*H + h
        u64 m = __ldg(&fired[lh]);
        float w = __ldg(&oW[lh * CC + c]);
        acc += w * (float)((m >> b) & 1ull);
    }
    part[blockIdx.x * (BB * CC) + t] = acc;
}

// Output stage 2: deterministic fixed-order reduction of partials.
__global__ void out_reduce_kernel(const float* __restrict__ part,
                                  float* __restrict__ out) {
    int t = threadIdx.x;
    if (t >= BB * CC) return;
    float s = 0.0f;
#pragma unroll
    for (int k = 0; k < OUT_BLOCKS; k++) s += part[k * (BB * CC) + t];
    int b = t & 63;
    int c = t >> 6;
    out[b * CC + c] = s;
}

// -------------------------------------------------------------------------
extern "C" void kernel_launch(void* const* d_in, const int* in_sizes, int n_in,
                              void* d_out, int out_size) {
    const float* x  = (const float*)d_in[0];
    const float* W0 = (const float*)d_in[1];
    const float* W1 = (const float*)d_in[2];
    const float* W2 = (const float*)d_in[3];
    const float* oW = (const float*)d_in[4];
    float* out = (float*)d_out;

    u64* act = nullptr;
    u64* fired = nullptr;
    float* part = nullptr;
    cudaGetSymbolAddress((void**)&act, g_act);
    cudaGetSymbolAddress((void**)&fired, g_fired);
    cudaGetSymbolAddress((void**)&part, g_part);

    zero_fired_kernel<<<(3 * HN + 255) / 256, 256>>>();
    encode_kernel<<<(P0 + 255) / 256, 256>>>(x);
    // one warp per (neuron, segment): 8192 warps
    layer_kernel<P0><<<1024, 256>>>(W0, act, fired);
    layer_kernel<HN><<<1024, 256>>>(W1, fired, fired + HN);
    layer_kernel<HN><<<1024, 256>>>(W2, fired + HN, fired + 2 * HN);
    out_partial_kernel<<<OUT_BLOCKS, BB * CC>>>(oW, fired, part);
    out_reduce_kernel<<<1, BB * CC>>>(part, out);
}

// round 5
// speedup vs baseline: 1.3086x; 1.3086x over previous
#include <cuda_runtime.h>
#include <cstdint>

#define NUM_BITS 16
#define THETA 8
#define HN 4096
#define FF 128
#define CC 10
#define BB 64
#define P0 (FF * NUM_BITS)   // 2048

#define OUT_BLOCKS 96
#define LH_TOTAL (3 * HN)                      // 12288
#define LH_PER_BLOCK (LH_TOTAL / OUT_BLOCKS)   // 128

typedef unsigned long long u64;

// Scratch (device globals: no allocation allowed in kernel_launch)
__device__ u64 g_act[P0];          // layer-0 input masks
__device__ u64 g_fired[3 * HN];    // per-layer fired masks
__device__ float g_part[OUT_BLOCKS * BB * CC];  // output partial sums

// -------------------------------------------------------------------------
// Encode: x[B,F] -> g_act[p], p = f*16 + t, bit b = (x[b,f] >= (t+1)/17)
// -------------------------------------------------------------------------
__global__ void encode_kernel(const float* __restrict__ x) {
    int p = blockIdx.x * blockDim.x + threadIdx.x;
    if (p >= P0) return;
    int f = p >> 4;
    int t = p & 15;
    float thr = (float)(t + 1) * (1.0f / (float)(NUM_BITS + 1));
    u64 m = 0ull;
#pragma unroll
    for (int b = 0; b < BB; b++) {
        float v = __ldg(&x[b * FF + f]);
        m |= ((u64)(v >= thr)) << b;
    }
    g_act[p] = m;
}

// -------------------------------------------------------------------------
// Layer: one warp per NEURON. Lanes 0-15 stream segment 0, lanes 16-31
// segment 1 (256B coalesced per half). Per-lane signed bit-sliced counters
// over all 64 batches: 7 planes of u64, two's complement, values in
// [-32,32]. Hit (weight != 0, ~2 per lane) adds +m or -m:
//   +m : addend planes (m,0,0,0,0,0,0)
//   -m : addend planes (m,m,m,m,m,m,m)   (-1 == 0b1111111)
// Epilogue: 4-round shfl butterfly within each 16-lane half, fire test
// fm = ~sign & (bit3|bit4|bit5), OR halves via one shfl, plain store.
// -------------------------------------------------------------------------
__device__ __forceinline__ void proc_vec(uint4 v, int i, int sub,
                                         const u64* __restrict__ act,
                                         u64* c) {
    if (v.x | v.y | v.z | v.w) {
        int pbase = i * 64 + sub * 4;
        unsigned comp[4] = {v.x, v.y, v.z, v.w};
#pragma unroll
        for (int j = 0; j < 4; j++) {
            unsigned wb = comp[j];
            if (wb) {
                u64 m = __ldg(&act[pbase + j]);
                u64 neg = (u64)0 - (u64)(wb >> 31);  // all-ones if weight<0
                u64 a = m, carry = 0;
#pragma unroll
                for (int k = 0; k < 7; k++) {
                    u64 ck = c[k];
                    u64 x = ck ^ a;
                    c[k] = x ^ carry;
                    carry = (ck & a) | (carry & x);
                    a = m & neg;   // planes 1..6 of addend
                }
            }
        }
    }
}

template <int P>
__global__ __launch_bounds__(256) void layer_kernel(
    const float* __restrict__ W,
    const u64* __restrict__ act,
    u64* __restrict__ fired) {
    int h = (blockIdx.x * blockDim.x + threadIdx.x) >> 5;   // warp = neuron
    int lane = threadIdx.x & 31;
    if (h >= HN) return;
    int half = lane >> 4;   // segment s
    int sub = lane & 15;

    const uint4* row =
        (const uint4*)(W + ((size_t)h * 2 + half) * (size_t)P);
    u64 c[7] = {0, 0, 0, 0, 0, 0, 0};

    constexpr int NIT = P / 64;   // uint4 loads per lane: 32 or 64
#pragma unroll 2
    for (int i = 0; i < NIT; i += 4) {
        uint4 v0 = __ldg(&row[(i + 0) * 16 + sub]);
        uint4 v1 = __ldg(&row[(i + 1) * 16 + sub]);
        uint4 v2 = __ldg(&row[(i + 2) * 16 + sub]);
        uint4 v3 = __ldg(&row[(i + 3) * 16 + sub]);
        proc_vec(v0, i + 0, sub, act, c);
        proc_vec(v1, i + 1, sub, act, c);
        proc_vec(v2, i + 2, sub, act, c);
        proc_vec(v3, i + 3, sub, act, c);
    }

    // Bit-sliced butterfly reduction within each 16-lane half.
#pragma unroll
    for (int off = 1; off < 16; off <<= 1) {
        u64 t[7];
#pragma unroll
        for (int k = 0; k < 7; k++)
            t[k] = __shfl_xor_sync(0xffffffffu, c[k], off);
        u64 carry = 0;
#pragma unroll
        for (int k = 0; k < 7; k++) {
            u64 ck = c[k], bk = t[k];
            u64 x = ck ^ bk;
            c[k] = x ^ carry;
            carry = (ck & bk) | (carry & x);
        }
    }

    // fired iff count >= 8: sign clear and any of bits 3..5 set.
    u64 fm = ~c[6] & (c[3] | c[4] | c[5]);
    // OR the two segments' masks together across halves.
    fm |= __shfl_xor_sync(0xffffffffu, fm, 16);
    if (lane == 0) fired[h] = fm;
}

// -------------------------------------------------------------------------
// Output stage 1: partial sums over (l,h) slices.
// thread t: c = t/64, b = t%64 -> outW load warp-uniform, fired block-uniform.
// -------------------------------------------------------------------------
__global__ __launch_bounds__(640) void out_partial_kernel(
    const float* __restrict__ oW,
    const u64* __restrict__ fired,
    float* __restrict__ part) {
    int t = threadIdx.x;          // 0..639
    int b = t & 63;
    int c = t >> 6;
    int start = blockIdx.x * LH_PER_BLOCK;
    float acc = 0.0f;
#pragma unroll 8
    for (int i = 0; i < LH_PER_BLOCK; i++) {
        int lh = start + i;       // flat l*H + h
        u64 m = __ldg(&fired[lh]);
        float w = __ldg(&oW[lh * CC + c]);
        acc += w * (float)((m >> b) & 1ull);
    }
    part[blockIdx.x * (BB * CC) + t] = acc;
}

// Output stage 2: deterministic fixed-order reduction of partials.
__global__ void out_reduce_kernel(const float* __restrict__ part,
                                  float* __restrict__ out) {
    int t = threadIdx.x;
    if (t >= BB * CC) return;
    float s = 0.0f;
#pragma unroll
    for (int k = 0; k < OUT_BLOCKS; k++) s += part[k * (BB * CC) + t];
    int b = t & 63;
    int c = t >> 6;
    out[b * CC + c] = s;
}

// -------------------------------------------------------------------------
extern "C" void kernel_launch(void* const* d_in, const int* in_sizes, int n_in,
                              void* d_out, int out_size) {
    const float* x  = (const float*)d_in[0];
    const float* W0 = (const float*)d_in[1];
    const float* W1 = (const float*)d_in[2];
    const float* W2 = (const float*)d_in[3];
    const float* oW = (const float*)d_in[4];
    float* out = (float*)d_out;

    u64* act = nullptr;
    u64* fired = nullptr;
    float* part = nullptr;
    cudaGetSymbolAddress((void**)&act, g_act);
    cudaGetSymbolAddress((void**)&fired, g_fired);
    cudaGetSymbolAddress((void**)&part, g_part);

    encode_kernel<<<(P0 + 255) / 256, 256>>>(x);
    // one warp per neuron: 4096 warps = 512 blocks * 8 warps
    layer_kernel<P0><<<512, 256>>>(W0, act, fired);
    layer_kernel<HN><<<512, 256>>>(W1, fired, fired + HN);
    layer_kernel<HN><<<512, 256>>>(W2, fired + HN, fired + 2 * HN);
    out_partial_kernel<<<OUT_BLOCKS, BB * CC>>>(oW, fired, part);
    out_reduce_kernel<<<1, BB * CC>>>(part, out);
}

// round 6
// speedup vs baseline: 1.3706x; 1.0474x over previous
#include <cuda_runtime.h>
#include <cstdint>

#define NUM_BITS 16
#define THETA 8
#define HN 4096
#define FF 128
#define CC 10
#define BB 64
#define P0 (FF * NUM_BITS)   // 2048

#define OUT_BLOCKS 192
#define LH_TOTAL (3 * HN)                      // 12288
#define LH_PER_BLOCK (LH_TOTAL / OUT_BLOCKS)   // 64

typedef unsigned long long u64;

// Scratch (device globals: no allocation allowed in kernel_launch)
__device__ u64 g_act[P0];          // layer-0 input masks
__device__ u64 g_fired[3 * HN];    // per-layer fired masks
__device__ float g_part[OUT_BLOCKS * BB * CC];  // output partial sums

// -------------------------------------------------------------------------
// Encode: x[B,F] -> g_act[p], p = f*16 + t, bit b = (x[b,f] >= (t+1)/17)
// -------------------------------------------------------------------------
__global__ void encode_kernel(const float* __restrict__ x) {
    int p = blockIdx.x * blockDim.x + threadIdx.x;
    if (p >= P0) return;
    int f = p >> 4;
    int t = p & 15;
    float thr = (float)(t + 1) * (1.0f / (float)(NUM_BITS + 1));
    u64 m = 0ull;
#pragma unroll
    for (int b = 0; b < BB; b++) {
        float v = __ldg(&x[b * FF + f]);
        m |= ((u64)(v >= thr)) << b;
    }
    g_act[p] = m;
}

// -------------------------------------------------------------------------
// Hit: add +m (weight>0) or -m (weight<0) into 7-plane signed bit-sliced
// counters over 64 batches (two's complement, values always in [-32,32]).
//   +m : addend planes (m,0,0,0,0,0,0)
//   -m : addend planes (m,m,m,m,m,m,m)
// -------------------------------------------------------------------------
__device__ __forceinline__ void hit_add(u64* c, u64 m, unsigned wb) {
    u64 neg = (u64)0 - (u64)(wb >> 31);  // all-ones if weight negative
    u64 a = m, carry = 0;
#pragma unroll
    for (int k = 0; k < 7; k++) {
        u64 ck = c[k];
        u64 x = ck ^ a;
        c[k] = x ^ carry;
        carry = (ck & a) | (carry & x);
        a = m & neg;   // planes 1..6 of addend
    }
}

// Process a group of 4 uint4 weight vectors (base uint4 index i0).
// Single grouped nonzero test (~88% skip) before per-vector work.
__device__ __forceinline__ void proc_group(const uint4* v, int i0, int sub,
                                           const u64* __restrict__ act,
                                           u64* c) {
    unsigned any = (v[0].x | v[0].y) | (v[0].z | v[0].w)
                 | (v[1].x | v[1].y) | (v[1].z | v[1].w)
                 | (v[2].x | v[2].y) | (v[2].z | v[2].w)
                 | (v[3].x | v[3].y) | (v[3].z | v[3].w);
    if (any) {
#pragma unroll
        for (int k = 0; k < 4; k++) {
            uint4 w = v[k];
            if (w.x | w.y | w.z | w.w) {
                int pbase = (i0 + k) * 64 + sub * 4;
                unsigned comp[4] = {w.x, w.y, w.z, w.w};
#pragma unroll
                for (int j = 0; j < 4; j++) {
                    if (comp[j]) hit_add(c, __ldg(&act[pbase + j]), comp[j]);
                }
            }
        }
    }
}

// -------------------------------------------------------------------------
// Layer: one warp per NEURON. Lanes 0-15 stream segment 0, lanes 16-31
// segment 1 (256B coalesced per half). Double-buffered 4-load pipeline keeps
// loads in flight while the previous group is processed. Epilogue: 4-round
// shfl butterfly within each 16-lane half, exact bit-sliced >=8 test, OR the
// two halves via one shfl, plain store.
// -------------------------------------------------------------------------
template <int P>
__global__ __launch_bounds__(128) void layer_kernel(
    const float* __restrict__ W,
    const u64* __restrict__ act,
    u64* __restrict__ fired) {
    int h = (blockIdx.x * blockDim.x + threadIdx.x) >> 5;   // warp = neuron
    int lane = threadIdx.x & 31;
    if (h >= HN) return;
    int half = lane >> 4;   // segment s
    int sub = lane & 15;

    const uint4* row =
        (const uint4*)(W + ((size_t)h * 2 + half) * (size_t)P);
    u64 c[7] = {0, 0, 0, 0, 0, 0, 0};

    constexpr int NG = P / 256;   // groups of 4 uint4 loads: 8 or 16
    uint4 cur[4], nxt[4];
#pragma unroll
    for (int j = 0; j < 4; j++) cur[j] = __ldg(&row[j * 16 + sub]);

#pragma unroll 4
    for (int g = 1; g < NG; g++) {
#pragma unroll
        for (int j = 0; j < 4; j++)
            nxt[j] = __ldg(&row[(g * 4 + j) * 16 + sub]);
        proc_group(cur, (g - 1) * 4, sub, act, c);
#pragma unroll
        for (int j = 0; j < 4; j++) cur[j] = nxt[j];
    }
    proc_group(cur, (NG - 1) * 4, sub, act, c);

    // Bit-sliced butterfly reduction within each 16-lane half.
#pragma unroll
    for (int off = 1; off < 16; off <<= 1) {
        u64 t[7];
#pragma unroll
        for (int k = 0; k < 7; k++)
            t[k] = __shfl_xor_sync(0xffffffffu, c[k], off);
        u64 carry = 0;
#pragma unroll
        for (int k = 0; k < 7; k++) {
            u64 ck = c[k], bk = t[k];
            u64 x = ck ^ bk;
            c[k] = x ^ carry;
            carry = (ck & bk) | (carry & x);
        }
    }

    // fired iff count >= 8: sign plane clear and any of bits 3..5 set.
    u64 fm = ~c[6] & (c[3] | c[4] | c[5]);
    // OR the two segments' masks together across halves.
    fm |= __shfl_xor_sync(0xffffffffu, fm, 16);
    if (lane == 0) fired[h] = fm;
}

// -------------------------------------------------------------------------
// Output stage 1: partial sums over (l,h) slices.
// thread t: c = t/64, b = t%64 -> outW load warp-uniform, fired block-uniform.
// -------------------------------------------------------------------------
__global__ __launch_bounds__(640) void out_partial_kernel(
    const float* __restrict__ oW,
    const u64* __restrict__ fired,
    float* __restrict__ part) {
    int t = threadIdx.x;          // 0..639
    int b = t & 63;
    int c = t >> 6;
    int start = blockIdx.x * LH_PER_BLOCK;
    float acc = 0.0f;
#pragma unroll 16
    for (int i = 0; i < LH_PER_BLOCK; i++) {
        int lh = start + i;       // flat l*H + h
        u64 m = __ldg(&fired[lh]);
        float w = __ldg(&oW[lh * CC + c]);
        acc += w * (float)((m >> b) & 1ull);
    }
    part[blockIdx.x * (BB * CC) + t] = acc;
}

// Output stage 2: deterministic fixed-order reduction of partials.
__global__ void out_reduce_kernel(const float* __restrict__ part,
                                  float* __restrict__ out) {
    int t = threadIdx.x;
    if (t >= BB * CC) return;
    float s = 0.0f;
#pragma unroll
    for (int k = 0; k < OUT_BLOCKS; k++) s += part[k * (BB * CC) + t];
    int b = t & 63;
    int c = t >> 6;
    out[b * CC + c] = s;
}

// -------------------------------------------------------------------------
extern "C" void kernel_launch(void* const* d_in, const int* in_sizes, int n_in,
                              void* d_out, int out_size) {
    const float* x  = (const float*)d_in[0];
    const float* W0 = (const float*)d_in[1];
    const float* W1 = (const float*)d_in[2];
    const float* W2 = (const float*)d_in[3];
    const float* oW = (const float*)d_in[4];
    float* out = (float*)d_out;

    u64* act = nullptr;
    u64* fired = nullptr;
    float* part = nullptr;
    cudaGetSymbolAddress((void**)&act, g_act);
    cudaGetSymbolAddress((void**)&fired, g_fired);
    cudaGetSymbolAddress((void**)&part, g_part);

    encode_kernel<<<(P0 + 255) / 256, 256>>>(x);
    // one warp per neuron: 4096 warps = 1024 blocks * 4 warps
    layer_kernel<P0><<<1024, 128>>>(W0, act, fired);
    layer_kernel<HN><<<1024, 128>>>(W1, fired, fired + HN);
    layer_kernel<HN><<<1024, 128>>>(W2, fired + HN, fired + 2 * HN);
    out_partial_kernel<<<OUT_BLOCKS, BB * CC>>>(oW, fired, part);
    out_reduce_kernel<<<1, BB * CC>>>(part, out);
}